// round 16
// baseline (speedup 1.0000x reference)
#include <cuda_runtime.h>
#include <cuda_fp16.h>

#define N_NODES 50000
#define N_EDGES 800000
#define IN_F    64
#define OUT_F   32
#define N_STEPS 20
#define LR      0.1f
#define SLOPE   0.2f
#define FULLMASK 0xFFFFFFFFu

#define SCAN_TPB 1024
#define SCAN_BLOCKS ((N_NODES + SCAN_TPB - 1) / SCAN_TPB)   // 49

// two nodes per warp
#define N_WARPS ((N_NODES + 1) / 2)                          // 25000
#define DEG_BINS 128

// ---------------- scratch (device globals; no allocation allowed) ----------------
__device__ __half g_th[N_NODES * OUT_F];      // transformed rows in fp16 (64B/row)
__device__ float g_mu[N_NODES * OUT_F];
__device__ float g_es[2 * N_NODES];   // double-buffered (parity)
__device__ float g_ed[2 * N_NODES];
__device__ int   g_degi[N_NODES];
__device__ int   g_rowstart[N_NODES + 1];
__device__ int   g_fill[N_NODES];
__device__ int   g_bsum[SCAN_BLOCKS];
__device__ int   g_boff[SCAN_BLOCKS];
__device__ int   g_csr_src[N_EDGES];
__device__ int   g_csr_eid[N_EDGES];
__device__ int   g_hist[DEG_BINS];
__device__ int   g_hfill[DEG_BINS];
__device__ int   g_perm[N_NODES];     // nodes sorted by (clamped) degree

__device__ __forceinline__ float leaky(float x) {
    return (x > 0.0f) ? x : SLOPE * x;
}

// load 4 fp16 features (8 bytes) and accumulate into float4 with weight evj
__device__ __forceinline__ void acc_half4(float4& acc, float evj,
                                          const __half* __restrict__ p) {
    uint2 u = *(const uint2*)p;
    __half2 h0 = *reinterpret_cast<__half2*>(&u.x);
    __half2 h1 = *reinterpret_cast<__half2*>(&u.y);
    float2 f0 = __half22float2(h0);
    float2 f1 = __half22float2(h1);
    acc.x = fmaf(evj, f0.x, acc.x);
    acc.y = fmaf(evj, f0.y, acc.y);
    acc.z = fmaf(evj, f1.x, acc.z);
    acc.w = fmaf(evj, f1.y, acc.w);
}

// ---------------- setup kernels ----------------

__global__ void init_kernel() {
    int i = blockIdx.x * blockDim.x + threadIdx.x;
    if (i < N_NODES) g_degi[i] = 0;
    if (i < DEG_BINS) g_hist[i] = 0;
}

// transformed = mu_upper @ W^T -> fp16. Warp per node (grid-stride), lane = out feature.
__global__ void gemm_kernel(const float* __restrict__ mu_upper,
                            const float* __restrict__ W) {
    __shared__ float Wt[IN_F][OUT_F];   // Wt[k][f] = W[f*IN_F + k]
    for (int i = threadIdx.x; i < IN_F * OUT_F; i += blockDim.x) {
        int k = i >> 5, f = i & 31;
        Wt[k][f] = W[f * IN_F + k];
    }
    __syncthreads();

    int lane = threadIdx.x & 31;
    int warpsPerGrid = (gridDim.x * blockDim.x) >> 5;
    int w0 = (blockIdx.x * blockDim.x + threadIdx.x) >> 5;

    for (int n = w0; n < N_NODES; n += warpsPerGrid) {
        const float* row = mu_upper + n * IN_F;
        float r0 = row[lane];
        float r1 = row[lane + 32];
        float acc = 0.0f;
#pragma unroll
        for (int k = 0; k < 32; ++k)
            acc = fmaf(__shfl_sync(FULLMASK, r0, k), Wt[k][lane], acc);
#pragma unroll
        for (int k = 0; k < 32; ++k)
            acc = fmaf(__shfl_sync(FULLMASK, r1, k), Wt[32 + k][lane], acc);
        g_th[n * OUT_F + lane] = __float2half(acc);
    }
}

__global__ void count_kernel(const int* __restrict__ dst) {
    int e = blockIdx.x * blockDim.x + threadIdx.x;
    if (e >= N_EDGES) return;
    atomicAdd(&g_degi[dst[e]], 1);
}

__global__ void scanA_kernel() {
    __shared__ int warp_sums[32];
    int tid  = threadIdx.x;
    int lane = tid & 31;
    int wid  = tid >> 5;
    int idx  = blockIdx.x * SCAN_TPB + tid;

    int v = (idx < N_NODES) ? g_degi[idx] : 0;
    int x = v;
#pragma unroll
    for (int off = 1; off < 32; off <<= 1) {
        int y = __shfl_up_sync(FULLMASK, x, off);
        if (lane >= off) x += y;
    }
    if (lane == 31) warp_sums[wid] = x;
    __syncthreads();
    if (wid == 0) {
        int w = warp_sums[lane];
#pragma unroll
        for (int off = 1; off < 32; off <<= 1) {
            int y = __shfl_up_sync(FULLMASK, w, off);
            if (lane >= off) w += y;
        }
        warp_sums[lane] = w;
    }
    __syncthreads();
    int incl = x + ((wid > 0) ? warp_sums[wid - 1] : 0);
    if (idx < N_NODES) g_rowstart[idx] = incl - v;
    if (tid == SCAN_TPB - 1) g_bsum[blockIdx.x] = incl;
}

__global__ void scanB_kernel() {
    __shared__ int s[64];
    int t = threadIdx.x;
    int v = (t < SCAN_BLOCKS) ? g_bsum[t] : 0;
    s[t] = v;
    __syncthreads();
#pragma unroll
    for (int off = 1; off < 64; off <<= 1) {
        int x = (t >= off) ? s[t - off] : 0;
        __syncthreads();
        s[t] += x;
        __syncthreads();
    }
    if (t < SCAN_BLOCKS) g_boff[t] = s[t] - v;
    if (t == 63) g_rowstart[N_NODES] = s[63];
}

// add block offsets, init fill cursors, and histogram degrees for the sort
__global__ void scanC_kernel() {
    int idx = blockIdx.x * blockDim.x + threadIdx.x;
    if (idx >= N_NODES) return;
    int r = g_rowstart[idx] + g_boff[idx >> 10];
    g_rowstart[idx] = r;
    g_fill[idx] = r;
    atomicAdd(&g_hist[min(g_degi[idx], DEG_BINS - 1)], 1);
}

__global__ void scatter_kernel(const int* __restrict__ src,
                               const int* __restrict__ dst) {
    int e = blockIdx.x * blockDim.x + threadIdx.x;
    if (e >= N_EDGES) return;
    int pos = atomicAdd(&g_fill[dst[e]], 1);
    g_csr_src[pos] = src[e];
    g_csr_eid[pos] = e;
}

// exclusive scan of the 128-bin degree histogram (one block)
__global__ void scanH_kernel() {
    __shared__ int s[DEG_BINS];
    int t = threadIdx.x;
    int v = g_hist[t];
    s[t] = v;
    __syncthreads();
#pragma unroll
    for (int off = 1; off < DEG_BINS; off <<= 1) {
        int x = (t >= off) ? s[t - off] : 0;
        __syncthreads();
        s[t] += x;
        __syncthreads();
    }
    g_hfill[t] = s[t] - v;   // exclusive
}

// scatter nodes into degree-sorted permutation
__global__ void permute_kernel() {
    int i = blockIdx.x * blockDim.x + threadIdx.x;
    if (i >= N_NODES) return;
    int bin = min(g_degi[i], DEG_BINS - 1);
    int pos = atomicAdd(&g_hfill[bin], 1);
    g_perm[pos] = i;
}

// ---------------- step 0: uniform-alpha top-down + node update (mu0 = 0) --------
// two (degree-matched) nodes per warp.
__global__ void __launch_bounds__(256)
step0_kernel(const float* __restrict__ a_vec) {
    int t = blockIdx.x * blockDim.x + threadIdx.x;
    int wid = t >> 5;
    if (wid >= N_WARPS) return;
    int lane = t & 31;
    int h  = lane >> 4;          // which node in warp
    int hl = lane & 15;          // lane within half
    int eq = hl >> 3;            // edge-quarter (0/1)
    int fl = hl & 7;             // float4 feature slice
    int n = __ldg(&g_perm[2 * wid + h]);

    int beg = g_rowstart[n], end = g_rowstart[n + 1];
    int deg = end - beg;
    int degO = __shfl_xor_sync(FULLMASK, deg, 16);
    int rounds = (max(deg, degO) + 15) >> 4;

    float4 acc = make_float4(0.f, 0.f, 0.f, 0.f);
    for (int r = 0; r < rounds; ++r) {
        int eb = r << 4;
        int s = 0;
        if (eb + hl < deg) s = __ldg(&g_csr_src[beg + eb + hl]);
#pragma unroll
        for (int g = 0; g < 8; ++g) {
            int e = (g << 1) + eq;
            int sj = __shfl_sync(FULLMASK, s, (h << 4) + e);
            if (eb + e < deg)
                acc_half4(acc, 1.0f, g_th + sj * OUT_F + fl * 4);
        }
    }
    // reduce across eq (within half)
    acc.x += __shfl_xor_sync(FULLMASK, acc.x, 8);
    acc.y += __shfl_xor_sync(FULLMASK, acc.y, 8);
    acc.z += __shfl_xor_sync(FULLMASK, acc.z, 8);
    acc.w += __shfl_xor_sync(FULLMASK, acc.w, 8);

    float inv = 1.0f / ((float)deg + 1e-8f);
    float4 mh = make_float4(fmaxf(acc.x * inv, 0.f), fmaxf(acc.y * inv, 0.f),
                            fmaxf(acc.z * inv, 0.f), fmaxf(acc.w * inv, 0.f));
    const float4 as = *(const float4*)(a_vec + fl * 4);
    const float4 ad = *(const float4*)(a_vec + OUT_F + fl * 4);
    float ps = -(mh.x * as.x + mh.y * as.y + mh.z * as.z + mh.w * as.w);
    float pd = -(mh.x * ad.x + mh.y * ad.y + mh.z * ad.z + mh.w * ad.w);
#pragma unroll
    for (int off = 1; off <= 4; off <<= 1) {
        ps += __shfl_xor_sync(FULLMASK, ps, off);
        pd += __shfl_xor_sync(FULLMASK, pd, off);
    }
    if (hl == 0) {
        g_es[n] = ps;
        g_ed[n] = pd;
    }
    if (eq == 0)
        *(float4*)(g_mu + n * OUT_F + fl * 4) =
            make_float4(LR * mh.x, LR * mh.y, LR * mh.z, LR * mh.w);
}

// ---------------- fused step: softmax + aggregate + node update ----------------
// two degree-matched nodes per warp; max-free softmax.
// mode 0: intermediate (writes mu, es/ed[out_par]); mode 1: final outputs.
__global__ void __launch_bounds__(256)
fused_step_kernel(const float* __restrict__ a_vec,
                  int in_par, int out_par, int mode,
                  float* __restrict__ out_mu,
                  float* __restrict__ out_err,
                  float* __restrict__ out_alpha) {
    int t = blockIdx.x * blockDim.x + threadIdx.x;
    int wid = t >> 5;
    if (wid >= N_WARPS) return;
    int lane = t & 31;
    int h  = lane >> 4;
    int hl = lane & 15;
    int eq = hl >> 3;
    int fl = hl & 7;
    int n = __ldg(&g_perm[2 * wid + h]);

    const float* __restrict__ es_in = g_es + in_par * N_NODES;
    const float* __restrict__ ed_in = g_ed + in_par * N_NODES;

    int beg = g_rowstart[n], end = g_rowstart[n + 1];
    int deg = end - beg;
    float ed_n = __ldg(&ed_in[n]);

    int degO = __shfl_xor_sync(FULLMASK, deg, 16);
    int rounds = (max(deg, degO) + 15) >> 4;

    float sm = 0.0f;
    float4 acc = make_float4(0.f, 0.f, 0.f, 0.f);

    for (int r = 0; r < rounds; ++r) {
        int eb = r << 4;
        int s = 0;
        float ev = 0.0f;
        if (eb + hl < deg) {
            s = __ldg(&g_csr_src[beg + eb + hl]);
            ev = __expf(leaky(__ldg(&es_in[s]) + ed_n));
        }
        sm += ev;
#pragma unroll
        for (int g = 0; g < 8; ++g) {
            int e = (g << 1) + eq;
            int src_lane = (h << 4) + e;
            int   sj  = __shfl_sync(FULLMASK, s,  src_lane);
            float evj = __shfl_sync(FULLMASK, ev, src_lane);
            if (eb + e < deg)
                acc_half4(acc, evj, g_th + sj * OUT_F + fl * 4);
        }
    }

    // sum reduction within half (4 levels)
#pragma unroll
    for (int off = 8; off >= 1; off >>= 1)
        sm += __shfl_xor_sync(FULLMASK, sm, off);
    float inv = 1.0f / (sm + 1e-8f);

    // reduce acc across eq (1 level, within half)
    acc.x += __shfl_xor_sync(FULLMASK, acc.x, 8);
    acc.y += __shfl_xor_sync(FULLMASK, acc.y, 8);
    acc.z += __shfl_xor_sync(FULLMASK, acc.z, 8);
    acc.w += __shfl_xor_sync(FULLMASK, acc.w, 8);

    if (mode == 1) {
        // emit alpha (recompute scores; one-time final pass)
        for (int r = 0; r < rounds; ++r) {
            int i = beg + (r << 4) + hl;
            if ((r << 4) + hl < deg) {
                int s = __ldg(&g_csr_src[i]);
                float ev = __expf(leaky(__ldg(&es_in[s]) + ed_n));
                out_alpha[g_csr_eid[i]] = ev * inv;
            }
        }
    }

    // -------- fused node update (float4 per lane over features fl*4..+3) ----
    int idx4 = n * OUT_F + fl * 4;
    float4 mh = make_float4(fmaxf(acc.x * inv, 0.f), fmaxf(acc.y * inv, 0.f),
                            fmaxf(acc.z * inv, 0.f), fmaxf(acc.w * inv, 0.f));
    float4 mu = *(const float4*)(g_mu + idx4);
    float4 er = make_float4(mu.x - mh.x, mu.y - mh.y, mu.z - mh.z, mu.w - mh.w);

    if (mode == 0) {
        const float4 as = *(const float4*)(a_vec + fl * 4);
        const float4 ad = *(const float4*)(a_vec + OUT_F + fl * 4);
        float ps = er.x * as.x + er.y * as.y + er.z * as.z + er.w * as.w;
        float pd = er.x * ad.x + er.y * ad.y + er.z * ad.z + er.w * ad.w;
#pragma unroll
        for (int off = 1; off <= 4; off <<= 1) {
            ps += __shfl_xor_sync(FULLMASK, ps, off);
            pd += __shfl_xor_sync(FULLMASK, pd, off);
        }
        if (hl == 0) {
            g_es[out_par * N_NODES + n] = ps;
            g_ed[out_par * N_NODES + n] = pd;
        }
        if (eq == 0) {
            float4 mun = make_float4(mu.x - LR * er.x, mu.y - LR * er.y,
                                     mu.z - LR * er.z, mu.w - LR * er.w);
            *(float4*)(g_mu + idx4) = mun;
        }
    } else {
        if (eq == 0) {
            *(float4*)(out_mu + idx4)  = mu;
            *(float4*)(out_err + idx4) = er;
        }
    }
}

// ---------------- launch ----------------
extern "C" void kernel_launch(void* const* d_in, const int* in_sizes, int n_in,
                              void* d_out, int out_size) {
    const float* mu_upper   = (const float*)d_in[0];
    const float* W          = (const float*)d_in[1];
    const float* a_vec      = (const float*)d_in[2];
    const int*   edge_index = (const int*)d_in[3];
    const int*   src = edge_index;
    const int*   dst = edge_index + N_EDGES;

    float* out       = (float*)d_out;
    float* out_mu    = out;
    float* out_err   = out + N_NODES * OUT_F;
    float* out_alpha = out + 2 * N_NODES * OUT_F;

    const int TPB = 256;
    const int nodeBlocks1 = (N_NODES + TPB - 1) / TPB;
    const int edgeBlocks  = (N_EDGES + TPB - 1) / TPB;
    const int warp2Blocks = (N_WARPS * 32 + TPB - 1) / TPB;   // 3125

    init_kernel<<<nodeBlocks1, TPB>>>();
    gemm_kernel<<<1024, TPB>>>(mu_upper, W);
    count_kernel<<<edgeBlocks, TPB>>>(dst);
    scanA_kernel<<<SCAN_BLOCKS, SCAN_TPB>>>();
    scanB_kernel<<<1, 64>>>();
    scanC_kernel<<<nodeBlocks1, TPB>>>();
    scatter_kernel<<<edgeBlocks, TPB>>>(src, dst);
    scanH_kernel<<<1, DEG_BINS>>>();
    permute_kernel<<<nodeBlocks1, TPB>>>();

    step0_kernel<<<warp2Blocks, TPB>>>(a_vec);

    for (int t = 1; t < N_STEPS; ++t) {
        fused_step_kernel<<<warp2Blocks, TPB>>>(
            a_vec, (t - 1) & 1, t & 1, 0, nullptr, nullptr, nullptr);
    }
    fused_step_kernel<<<warp2Blocks, TPB>>>(
        a_vec, (N_STEPS - 1) & 1, 0, 1, out_mu, out_err, out_alpha);
}

// round 17
// speedup vs baseline: 1.1652x; 1.1652x over previous
#include <cuda_runtime.h>
#include <cuda_fp16.h>

#define N_NODES 50000
#define N_EDGES 800000
#define IN_F    64
#define OUT_F   32
#define N_STEPS 20
#define LR      0.1f
#define SLOPE   0.2f
#define FULLMASK 0xFFFFFFFFu

#define SCAN_TPB 1024
#define SCAN_BLOCKS ((N_NODES + SCAN_TPB - 1) / SCAN_TPB)   // 49

// two nodes per warp
#define N_WARPS ((N_NODES + 1) / 2)                          // 25000

// ---------------- scratch (device globals; no allocation allowed) ----------------
__device__ __half g_th[N_NODES * OUT_F];      // transformed rows in fp16 (64B/row)
__device__ float g_mu[N_NODES * OUT_F];
__device__ float g_es[2 * N_NODES];   // double-buffered (parity)
__device__ float g_ed[2 * N_NODES];
__device__ int   g_degi[N_NODES];
__device__ int   g_rowstart[N_NODES + 1];
__device__ int   g_fill[N_NODES];
__device__ int   g_bsum[SCAN_BLOCKS];
__device__ int   g_boff[SCAN_BLOCKS];
__device__ int   g_csr_src[N_EDGES];
__device__ int   g_csr_eid[N_EDGES];

__device__ __forceinline__ float leaky(float x) {
    return (x > 0.0f) ? x : SLOPE * x;
}

// load 4 fp16 features (8 bytes) and accumulate into float4 with weight evj
__device__ __forceinline__ void acc_half4(float4& acc, float evj,
                                          const __half* __restrict__ p) {
    uint2 u = *(const uint2*)p;
    __half2 h0 = *reinterpret_cast<__half2*>(&u.x);
    __half2 h1 = *reinterpret_cast<__half2*>(&u.y);
    float2 f0 = __half22float2(h0);
    float2 f1 = __half22float2(h1);
    acc.x = fmaf(evj, f0.x, acc.x);
    acc.y = fmaf(evj, f0.y, acc.y);
    acc.z = fmaf(evj, f1.x, acc.z);
    acc.w = fmaf(evj, f1.y, acc.w);
}

// ---------------- setup kernels ----------------

__global__ void init_kernel() {
    int i = blockIdx.x * blockDim.x + threadIdx.x;
    if (i < N_NODES) g_degi[i] = 0;
}

// transformed = mu_upper @ W^T -> fp16. Warp per node (grid-stride), lane = out feature.
__global__ void gemm_kernel(const float* __restrict__ mu_upper,
                            const float* __restrict__ W) {
    __shared__ float Wt[IN_F][OUT_F];   // Wt[k][f] = W[f*IN_F + k]
    for (int i = threadIdx.x; i < IN_F * OUT_F; i += blockDim.x) {
        int k = i >> 5, f = i & 31;
        Wt[k][f] = W[f * IN_F + k];
    }
    __syncthreads();

    int lane = threadIdx.x & 31;
    int warpsPerGrid = (gridDim.x * blockDim.x) >> 5;
    int w0 = (blockIdx.x * blockDim.x + threadIdx.x) >> 5;

    for (int n = w0; n < N_NODES; n += warpsPerGrid) {
        const float* row = mu_upper + n * IN_F;
        float r0 = row[lane];
        float r1 = row[lane + 32];
        float acc = 0.0f;
#pragma unroll
        for (int k = 0; k < 32; ++k)
            acc = fmaf(__shfl_sync(FULLMASK, r0, k), Wt[k][lane], acc);
#pragma unroll
        for (int k = 0; k < 32; ++k)
            acc = fmaf(__shfl_sync(FULLMASK, r1, k), Wt[32 + k][lane], acc);
        g_th[n * OUT_F + lane] = __float2half(acc);
    }
}

__global__ void count_kernel(const int* __restrict__ dst) {
    int e = blockIdx.x * blockDim.x + threadIdx.x;
    if (e >= N_EDGES) return;
    atomicAdd(&g_degi[dst[e]], 1);
}

__global__ void scanA_kernel() {
    __shared__ int warp_sums[32];
    int tid  = threadIdx.x;
    int lane = tid & 31;
    int wid  = tid >> 5;
    int idx  = blockIdx.x * SCAN_TPB + tid;

    int v = (idx < N_NODES) ? g_degi[idx] : 0;
    int x = v;
#pragma unroll
    for (int off = 1; off < 32; off <<= 1) {
        int y = __shfl_up_sync(FULLMASK, x, off);
        if (lane >= off) x += y;
    }
    if (lane == 31) warp_sums[wid] = x;
    __syncthreads();
    if (wid == 0) {
        int w = warp_sums[lane];
#pragma unroll
        for (int off = 1; off < 32; off <<= 1) {
            int y = __shfl_up_sync(FULLMASK, w, off);
            if (lane >= off) w += y;
        }
        warp_sums[lane] = w;
    }
    __syncthreads();
    int incl = x + ((wid > 0) ? warp_sums[wid - 1] : 0);
    if (idx < N_NODES) g_rowstart[idx] = incl - v;
    if (tid == SCAN_TPB - 1) g_bsum[blockIdx.x] = incl;
}

__global__ void scanB_kernel() {
    __shared__ int s[64];
    int t = threadIdx.x;
    int v = (t < SCAN_BLOCKS) ? g_bsum[t] : 0;
    s[t] = v;
    __syncthreads();
#pragma unroll
    for (int off = 1; off < 64; off <<= 1) {
        int x = (t >= off) ? s[t - off] : 0;
        __syncthreads();
        s[t] += x;
        __syncthreads();
    }
    if (t < SCAN_BLOCKS) g_boff[t] = s[t] - v;
    if (t == 63) g_rowstart[N_NODES] = s[63];
}

__global__ void scanC_kernel() {
    int idx = blockIdx.x * blockDim.x + threadIdx.x;
    if (idx >= N_NODES) return;
    int r = g_rowstart[idx] + g_boff[idx >> 10];
    g_rowstart[idx] = r;
    g_fill[idx] = r;
}

__global__ void scatter_kernel(const int* __restrict__ src,
                               const int* __restrict__ dst) {
    int e = blockIdx.x * blockDim.x + threadIdx.x;
    if (e >= N_EDGES) return;
    int pos = atomicAdd(&g_fill[dst[e]], 1);
    g_csr_src[pos] = src[e];
    g_csr_eid[pos] = e;
}

// ---------------- step 0: uniform-alpha top-down + node update (mu0 = 0) --------
// two nodes per warp (identity mapping preserves coalescing).
__global__ void __launch_bounds__(256)
step0_kernel(const float* __restrict__ a_vec) {
    int t = blockIdx.x * blockDim.x + threadIdx.x;
    int wid = t >> 5;
    if (wid >= N_WARPS) return;
    int lane = t & 31;
    int h  = lane >> 4;          // which node in warp
    int hl = lane & 15;          // lane within half
    int eq = hl >> 3;            // edge-quarter (0/1)
    int fl = hl & 7;             // float4 feature slice
    int n = 2 * wid + h;         // N_NODES even -> always valid

    int beg = g_rowstart[n], end = g_rowstart[n + 1];
    int deg = end - beg;
    int degO = __shfl_xor_sync(FULLMASK, deg, 16);
    int rounds = (max(deg, degO) + 15) >> 4;

    float4 acc = make_float4(0.f, 0.f, 0.f, 0.f);
    for (int r = 0; r < rounds; ++r) {
        int eb = r << 4;
        int s = 0;
        if (eb + hl < deg) s = __ldg(&g_csr_src[beg + eb + hl]);
#pragma unroll
        for (int g = 0; g < 8; ++g) {
            int e = (g << 1) + eq;
            int sj = __shfl_sync(FULLMASK, s, (h << 4) + e);
            if (eb + e < deg)
                acc_half4(acc, 1.0f, g_th + sj * OUT_F + fl * 4);
        }
    }
    // reduce across eq (within half)
    acc.x += __shfl_xor_sync(FULLMASK, acc.x, 8);
    acc.y += __shfl_xor_sync(FULLMASK, acc.y, 8);
    acc.z += __shfl_xor_sync(FULLMASK, acc.z, 8);
    acc.w += __shfl_xor_sync(FULLMASK, acc.w, 8);

    float inv = 1.0f / ((float)deg + 1e-8f);
    float4 mh = make_float4(fmaxf(acc.x * inv, 0.f), fmaxf(acc.y * inv, 0.f),
                            fmaxf(acc.z * inv, 0.f), fmaxf(acc.w * inv, 0.f));
    const float4 as = *(const float4*)(a_vec + fl * 4);
    const float4 ad = *(const float4*)(a_vec + OUT_F + fl * 4);
    float ps = -(mh.x * as.x + mh.y * as.y + mh.z * as.z + mh.w * as.w);
    float pd = -(mh.x * ad.x + mh.y * ad.y + mh.z * ad.z + mh.w * ad.w);
#pragma unroll
    for (int off = 1; off <= 4; off <<= 1) {
        ps += __shfl_xor_sync(FULLMASK, ps, off);
        pd += __shfl_xor_sync(FULLMASK, pd, off);
    }
    if (hl == 0) {
        g_es[n] = ps;
        g_ed[n] = pd;
    }
    if (eq == 0)
        *(float4*)(g_mu + n * OUT_F + fl * 4) =
            make_float4(LR * mh.x, LR * mh.y, LR * mh.z, LR * mh.w);
}

// ---------------- fused step: softmax + aggregate + node update ----------------
// two nodes per warp; max-free softmax; cross-round batched score loads
// (both 16-edge blocks' csr_src/es gathers issued together -> MLP 2).
// mode 0: intermediate (writes mu, es/ed[out_par]); mode 1: final outputs.
__global__ void __launch_bounds__(256)
fused_step_kernel(const float* __restrict__ a_vec,
                  int in_par, int out_par, int mode,
                  float* __restrict__ out_mu,
                  float* __restrict__ out_err,
                  float* __restrict__ out_alpha) {
    int t = blockIdx.x * blockDim.x + threadIdx.x;
    int wid = t >> 5;
    if (wid >= N_WARPS) return;
    int lane = t & 31;
    int h  = lane >> 4;
    int hl = lane & 15;
    int eq = hl >> 3;
    int fl = hl & 7;
    int n = 2 * wid + h;

    const float* __restrict__ es_in = g_es + in_par * N_NODES;
    const float* __restrict__ ed_in = g_ed + in_par * N_NODES;

    int beg = g_rowstart[n], end = g_rowstart[n + 1];
    int deg = end - beg;
    float ed_n = __ldg(&ed_in[n]);

    int degO = __shfl_xor_sync(FULLMASK, deg, 16);
    int rounds = (max(deg, degO) + 15) >> 4;

    float sm = 0.0f;
    float4 acc = make_float4(0.f, 0.f, 0.f, 0.f);

    // ---- batched score phase for edges [0,32): both blocks' loads in flight
    int sA = 0, sB = 0;
    float evA = 0.0f, evB = 0.0f;
    {
        bool vA = (hl < deg);
        bool vB = (16 + hl < deg);
        if (vA) sA = __ldg(&g_csr_src[beg + hl]);
        if (vB) sB = __ldg(&g_csr_src[beg + 16 + hl]);
        float esA = vA ? __ldg(&es_in[sA]) : 0.0f;
        float esB = vB ? __ldg(&es_in[sB]) : 0.0f;
        if (vA) evA = __expf(leaky(esA + ed_n));
        if (vB) evB = __expf(leaky(esB + ed_n));
        sm = evA + evB;
    }

    // ---- accumulate edges [0,16)
#pragma unroll
    for (int g = 0; g < 8; ++g) {
        int e = (g << 1) + eq;
        int src_lane = (h << 4) + e;
        int   sj  = __shfl_sync(FULLMASK, sA,  src_lane);
        float evj = __shfl_sync(FULLMASK, evA, src_lane);
        if (e < deg)
            acc_half4(acc, evj, g_th + sj * OUT_F + fl * 4);
    }
    // ---- accumulate edges [16,32)
    if (rounds > 1) {
#pragma unroll
        for (int g = 0; g < 8; ++g) {
            int e = (g << 1) + eq;
            int src_lane = (h << 4) + e;
            int   sj  = __shfl_sync(FULLMASK, sB,  src_lane);
            float evj = __shfl_sync(FULLMASK, evB, src_lane);
            if (16 + e < deg)
                acc_half4(acc, evj, g_th + sj * OUT_F + fl * 4);
        }
    }
    // ---- residual rounds (deg > 32; rare)
    for (int r = 2; r < rounds; ++r) {
        int eb = r << 4;
        int s = 0;
        float ev = 0.0f;
        if (eb + hl < deg) {
            s = __ldg(&g_csr_src[beg + eb + hl]);
            ev = __expf(leaky(__ldg(&es_in[s]) + ed_n));
        }
        sm += ev;
#pragma unroll
        for (int g = 0; g < 8; ++g) {
            int e = (g << 1) + eq;
            int src_lane = (h << 4) + e;
            int   sj  = __shfl_sync(FULLMASK, s,  src_lane);
            float evj = __shfl_sync(FULLMASK, ev, src_lane);
            if (eb + e < deg)
                acc_half4(acc, evj, g_th + sj * OUT_F + fl * 4);
        }
    }

    // sum reduction within half (4 levels)
#pragma unroll
    for (int off = 8; off >= 1; off >>= 1)
        sm += __shfl_xor_sync(FULLMASK, sm, off);
    float inv = 1.0f / (sm + 1e-8f);

    // reduce acc across eq (1 level, within half)
    acc.x += __shfl_xor_sync(FULLMASK, acc.x, 8);
    acc.y += __shfl_xor_sync(FULLMASK, acc.y, 8);
    acc.z += __shfl_xor_sync(FULLMASK, acc.z, 8);
    acc.w += __shfl_xor_sync(FULLMASK, acc.w, 8);

    if (mode == 1) {
        // emit alpha: first two blocks from registers, residue re-read
        if (hl < deg)      out_alpha[g_csr_eid[beg + hl]]      = evA * inv;
        if (16 + hl < deg) out_alpha[g_csr_eid[beg + 16 + hl]] = evB * inv;
        for (int r = 2; r < rounds; ++r) {
            int i = beg + (r << 4) + hl;
            if ((r << 4) + hl < deg) {
                int s = __ldg(&g_csr_src[i]);
                float ev = __expf(leaky(__ldg(&es_in[s]) + ed_n));
                out_alpha[g_csr_eid[i]] = ev * inv;
            }
        }
    }

    // -------- fused node update (float4 per lane over features fl*4..+3) ----
    int idx4 = n * OUT_F + fl * 4;
    float4 mh = make_float4(fmaxf(acc.x * inv, 0.f), fmaxf(acc.y * inv, 0.f),
                            fmaxf(acc.z * inv, 0.f), fmaxf(acc.w * inv, 0.f));
    float4 mu = *(const float4*)(g_mu + idx4);
    float4 er = make_float4(mu.x - mh.x, mu.y - mh.y, mu.z - mh.z, mu.w - mh.w);

    if (mode == 0) {
        const float4 as = *(const float4*)(a_vec + fl * 4);
        const float4 ad = *(const float4*)(a_vec + OUT_F + fl * 4);
        float ps = er.x * as.x + er.y * as.y + er.z * as.z + er.w * as.w;
        float pd = er.x * ad.x + er.y * ad.y + er.z * ad.z + er.w * ad.w;
#pragma unroll
        for (int off = 1; off <= 4; off <<= 1) {
            ps += __shfl_xor_sync(FULLMASK, ps, off);
            pd += __shfl_xor_sync(FULLMASK, pd, off);
        }
        if (hl == 0) {
            g_es[out_par * N_NODES + n] = ps;
            g_ed[out_par * N_NODES + n] = pd;
        }
        if (eq == 0) {
            float4 mun = make_float4(mu.x - LR * er.x, mu.y - LR * er.y,
                                     mu.z - LR * er.z, mu.w - LR * er.w);
            *(float4*)(g_mu + idx4) = mun;
        }
    } else {
        if (eq == 0) {
            *(float4*)(out_mu + idx4)  = mu;
            *(float4*)(out_err + idx4) = er;
        }
    }
}

// ---------------- launch ----------------
extern "C" void kernel_launch(void* const* d_in, const int* in_sizes, int n_in,
                              void* d_out, int out_size) {
    const float* mu_upper   = (const float*)d_in[0];
    const float* W          = (const float*)d_in[1];
    const float* a_vec      = (const float*)d_in[2];
    const int*   edge_index = (const int*)d_in[3];
    const int*   src = edge_index;
    const int*   dst = edge_index + N_EDGES;

    float* out       = (float*)d_out;
    float* out_mu    = out;
    float* out_err   = out + N_NODES * OUT_F;
    float* out_alpha = out + 2 * N_NODES * OUT_F;

    const int TPB = 256;
    const int nodeBlocks1 = (N_NODES + TPB - 1) / TPB;
    const int edgeBlocks  = (N_EDGES + TPB - 1) / TPB;
    const int warp2Blocks = (N_WARPS * 32 + TPB - 1) / TPB;   // 3125

    init_kernel<<<nodeBlocks1, TPB>>>();
    gemm_kernel<<<1024, TPB>>>(mu_upper, W);
    count_kernel<<<edgeBlocks, TPB>>>(dst);
    scanA_kernel<<<SCAN_BLOCKS, SCAN_TPB>>>();
    scanB_kernel<<<1, 64>>>();
    scanC_kernel<<<nodeBlocks1, TPB>>>();
    scatter_kernel<<<edgeBlocks, TPB>>>(src, dst);

    step0_kernel<<<warp2Blocks, TPB>>>(a_vec);

    for (int t = 1; t < N_STEPS; ++t) {
        fused_step_kernel<<<warp2Blocks, TPB>>>(
            a_vec, (t - 1) & 1, t & 1, 0, nullptr, nullptr, nullptr);
    }
    fused_step_kernel<<<warp2Blocks, TPB>>>(
        a_vec, (N_STEPS - 1) & 1, 0, 1, out_mu, out_err, out_alpha);
}